// round 1
// baseline (speedup 1.0000x reference)
#include <cuda_runtime.h>
#include <cstdint>

// out[b, i, j, :] = pe[clamp(128 + j - i, 0, 256), :]
// B=4, S=512, D=128 (32 float4 per row). Pure HBM-write-bound.
//
// One warp handles one (i,j) row: lane l loads pe[rel] float4 #l (L2-resident,
// only 257 distinct pe rows) and stores it to all 4 batch copies.

#define S_DIM 512
#define D4 32              // D=128 floats = 32 float4
#define ROWS_PER_BLOCK 8   // 256 threads / 32 lanes

__global__ __launch_bounds__(256, 8)
void relpos_kernel(const float4* __restrict__ pe, float4* __restrict__ out) {
    const int row  = blockIdx.x * ROWS_PER_BLOCK + (threadIdx.x >> 5); // i*512 + j
    const int lane = threadIdx.x & 31;

    const int i = row >> 9;          // row / 512
    const int j = row & (S_DIM - 1); // row % 512

    int rel = 128 + j - i;
    rel = rel < 0 ? 0 : (rel > 256 ? 256 : rel);

    const float4 v = pe[rel * D4 + lane];

    const size_t o = (size_t)row * D4 + lane;
    const size_t bstride = (size_t)S_DIM * S_DIM * D4; // one batch in float4 units

    out[o]               = v;
    out[o +     bstride] = v;
    out[o + 2 * bstride] = v;
    out[o + 3 * bstride] = v;
}

extern "C" void kernel_launch(void* const* d_in, const int* in_sizes, int n_in,
                              void* d_out, int out_size) {
    // d_in[0] = x (int32 [4,512], unused)
    // d_in[1] = pe (float32 [512,128])
    const float4* pe = (const float4*)d_in[1];
    float4* out = (float4*)d_out;

    const int total_rows = S_DIM * S_DIM;            // 262144
    const int blocks = total_rows / ROWS_PER_BLOCK;  // 32768
    relpos_kernel<<<blocks, 256>>>(pe, out);
}

// round 4
// speedup vs baseline: 1.0072x; 1.0072x over previous
#include <cuda_runtime.h>
#include <cstdint>

// out[b, i, j, :] = pe[clamp(128 + j - i, 0, 256), :]
// B=4, S=512, D=128 (32 float4 per row). Pure HBM-write-bound.
//
// One warp handles TWO adjacent (i,j) rows: per row, lane l loads pe[rel]
// float4 #l (L2-resident; only 257 distinct pe rows) and streams it to all
// 4 batch copies with evict-first (.cs) stores so L2 drains writebacks
// eagerly and uniformly.

#define S_DIM 512
#define D4 32               // D=128 floats = 32 float4
#define WARPS_PER_BLOCK 8
#define ROWS_PER_WARP 2

__global__ __launch_bounds__(256, 8)
void relpos_kernel(const float4* __restrict__ pe, float4* __restrict__ out) {
    const int warp = blockIdx.x * WARPS_PER_BLOCK + (threadIdx.x >> 5);
    const int lane = threadIdx.x & 31;
    const int row0 = warp * ROWS_PER_WARP;

    const size_t bstride = (size_t)S_DIM * S_DIM * D4; // one batch in float4 units

    #pragma unroll
    for (int r = 0; r < ROWS_PER_WARP; ++r) {
        const int row = row0 + r;
        const int i = row >> 9;          // row / 512
        const int j = row & (S_DIM - 1); // row % 512

        int rel = 128 + j - i;
        rel = rel < 0 ? 0 : (rel > 256 ? 256 : rel);

        const float4 v = __ldg(&pe[rel * D4 + lane]);

        const size_t o = (size_t)row * D4 + lane;
        __stcs(&out[o],               v);
        __stcs(&out[o +     bstride], v);
        __stcs(&out[o + 2 * bstride], v);
        __stcs(&out[o + 3 * bstride], v);
    }
}

extern "C" void kernel_launch(void* const* d_in, const int* in_sizes, int n_in,
                              void* d_out, int out_size) {
    // d_in[0] = x (int32 [4,512], unused)
    // d_in[1] = pe (float32 [512,128])
    const float4* pe = (const float4*)d_in[1];
    float4* out = (float4*)d_out;

    const int total_rows = S_DIM * S_DIM;                              // 262144
    const int blocks = total_rows / (WARPS_PER_BLOCK * ROWS_PER_WARP); // 16384
    relpos_kernel<<<blocks, 256>>>(pe, out);
}